// round 11
// baseline (speedup 1.0000x reference)
#include <cuda_runtime.h>
#include <cuda_bf16.h>
#include <cstdint>

// TransINT scoring, single-pass quadratic form (R3 body), 4 samples per warp
// with prefetch.global.L2 of the NEXT sample's 7 rows issued while the
// current sample computes. Prefetch has no destination register, so the
// proven 48-reg schedule is preserved while DRAM latency for 75% of samples
// is converted to L2-hit latency.
//   re = heads[rel2head[r]] * rel2mult[r]        (r = pos_r; neg_r unused)
//   s_pos = ent[ph] + re - ent[pt];  s_neg = ent[nh] + re - ent[nt]
//   A = bases[r] (2 x 256); c = ATA^{-1} (A.s)
//   exact-solution identity: ||s - A^T c||^2 = s.s - c.(A.s)
// out[0:B) = pos, out[B:2B) = neg (float32)

#define D 256
#define WARPS_PER_BLOCK 8
#define SPW 4   // samples per warp (grid-strided)

__device__ __forceinline__ void prefetch_row_1k(const float* p, int lane) {
    // 32 lanes x 32B stride = 1KB row (8 lines, each requested by 4 lanes)
    asm volatile("prefetch.global.L2 [%0];" :: "l"(p + lane * 8));
}

__global__ __launch_bounds__(WARPS_PER_BLOCK * 32, 5)
void transint_kernel(const int* __restrict__ pos_h,
                     const int* __restrict__ pos_t,
                     const int* __restrict__ pos_r,
                     const int* __restrict__ neg_h,
                     const int* __restrict__ neg_t,
                     const float* __restrict__ ent_emb,   // E x D
                     const float* __restrict__ heads,     // K x D
                     const float* __restrict__ bases,     // R x 2 x D
                     const int* __restrict__ rel2head,
                     const float* __restrict__ rel2mult,
                     float* __restrict__ out,
                     int B)
{
    const int lane = threadIdx.x & 31;
    const int nw = gridDim.x * WARPS_PER_BLOCK;   // total warps in grid
    int s = blockIdx.x * WARPS_PER_BLOCK + (threadIdx.x >> 5);

    #pragma unroll 1
    for (int k = 0; k < SPW; ++k) {
        if (s >= B) return;

        // Per-sample indices (uniform across warp; broadcast loads)
        const int ph = pos_h[s];
        const int pt = pos_t[s];
        const int r  = pos_r[s];
        const int nh = neg_h[s];
        const int nt = neg_t[s];
        const int hd = rel2head[r];
        const float mult = rel2mult[r];

        // Contiguous split: float4 index = lane and lane+32 (512B per LDG)
        const int v0 = lane;
        const int v1 = lane + 32;

        const float4* __restrict__ Eph = (const float4*)(ent_emb + (size_t)ph * D);
        const float4* __restrict__ Ept = (const float4*)(ent_emb + (size_t)pt * D);
        const float4* __restrict__ Enh = (const float4*)(ent_emb + (size_t)nh * D);
        const float4* __restrict__ Ent = (const float4*)(ent_emb + (size_t)nt * D);
        const float4* __restrict__ Hd  = (const float4*)(heads   + (size_t)hd * D);
        const float4* __restrict__ A0p = (const float4*)(bases   + (size_t)r * 2 * D);
        const float4* __restrict__ A1p = (const float4*)(bases   + (size_t)r * 2 * D + D);

        // Current sample's 14 loads
        float4 hp0 = Eph[v0], hp1 = Eph[v1];
        float4 tp0 = Ept[v0], tp1 = Ept[v1];
        float4 hn0 = Enh[v0], hn1 = Enh[v1];
        float4 tn0 = Ent[v0], tn1 = Ent[v1];
        float4 re0 = Hd[v0],  re1 = Hd[v1];
        float4 a00 = A0p[v0], a01 = A0p[v1];
        float4 a10 = A1p[v0], a11 = A1p[v1];

        // Prefetch NEXT sample's rows into L2 (no destination registers)
        const int snext = s + nw;
        if (k + 1 < SPW && snext < B) {
            const int phN = pos_h[snext];
            const int ptN = pos_t[snext];
            const int rN  = pos_r[snext];
            const int nhN = neg_h[snext];
            const int ntN = neg_t[snext];
            const int hdN = rel2head[rN];
            prefetch_row_1k(ent_emb + (size_t)phN * D, lane);
            prefetch_row_1k(ent_emb + (size_t)ptN * D, lane);
            prefetch_row_1k(ent_emb + (size_t)nhN * D, lane);
            prefetch_row_1k(ent_emb + (size_t)ntN * D, lane);
            prefetch_row_1k(heads   + (size_t)hdN * D, lane);
            prefetch_row_1k(bases   + (size_t)rN * 2 * D, lane);
            prefetch_row_1k(bases   + (size_t)rN * 2 * D + D, lane);
        }

        // 9 streamed accumulators; single pass over the data
        float aa = 0.f, ab = 0.f, dd = 0.f;
        float as0p = 0.f, as1p = 0.f, ssp = 0.f;
        float as0n = 0.f, as1n = 0.f, ssn = 0.f;
        {
            const float* hpp = (const float*)&hp0; const float* hpq = (const float*)&hp1;
            const float* tpp = (const float*)&tp0; const float* tpq = (const float*)&tp1;
            const float* hnp = (const float*)&hn0; const float* hnq = (const float*)&hn1;
            const float* tnp = (const float*)&tn0; const float* tnq = (const float*)&tn1;
            const float* rep = (const float*)&re0; const float* req = (const float*)&re1;
            const float* a0p = (const float*)&a00; const float* a0q = (const float*)&a01;
            const float* a1p = (const float*)&a10; const float* a1q = (const float*)&a11;
            #pragma unroll
            for (int i = 0; i < 4; i++) {
                {
                    const float re = rep[i] * mult;
                    const float sv = hpp[i] + re - tpp[i];
                    const float nv = hnp[i] + re - tnp[i];
                    const float A0 = a0p[i], A1 = a1p[i];
                    aa   = fmaf(A0, A0, aa);
                    ab   = fmaf(A0, A1, ab);
                    dd   = fmaf(A1, A1, dd);
                    as0p = fmaf(A0, sv, as0p);
                    as1p = fmaf(A1, sv, as1p);
                    ssp  = fmaf(sv, sv, ssp);
                    as0n = fmaf(A0, nv, as0n);
                    as1n = fmaf(A1, nv, as1n);
                    ssn  = fmaf(nv, nv, ssn);
                }
                {
                    const float re = req[i] * mult;
                    const float sv = hpq[i] + re - tpq[i];
                    const float nv = hnq[i] + re - tnq[i];
                    const float A0 = a0q[i], A1 = a1q[i];
                    aa   = fmaf(A0, A0, aa);
                    ab   = fmaf(A0, A1, ab);
                    dd   = fmaf(A1, A1, dd);
                    as0p = fmaf(A0, sv, as0p);
                    as1p = fmaf(A1, sv, as1p);
                    ssp  = fmaf(sv, sv, ssp);
                    as0n = fmaf(A0, nv, as0n);
                    as1n = fmaf(A1, nv, as1n);
                    ssn  = fmaf(nv, nv, ssn);
                }
            }
        }

        // Fused butterfly allreduce of 9 scalars
        #pragma unroll
        for (int m = 16; m > 0; m >>= 1) {
            aa   += __shfl_xor_sync(0xffffffffu, aa,   m);
            ab   += __shfl_xor_sync(0xffffffffu, ab,   m);
            dd   += __shfl_xor_sync(0xffffffffu, dd,   m);
            as0p += __shfl_xor_sync(0xffffffffu, as0p, m);
            as1p += __shfl_xor_sync(0xffffffffu, as1p, m);
            ssp  += __shfl_xor_sync(0xffffffffu, ssp,  m);
            as0n += __shfl_xor_sync(0xffffffffu, as0n, m);
            as1n += __shfl_xor_sync(0xffffffffu, as1n, m);
            ssn  += __shfl_xor_sync(0xffffffffu, ssn,  m);
        }

        if (lane == 0) {
            const float det = aa * dd - ab * ab;
            float scp, scn;
            if (det != 0.0f) {
                // exact normal-equation solve -> ||proj||^2 = ss - c . As
                const float inv_det = 1.0f / det;
                const float c0p = ( dd * as0p - ab * as1p) * inv_det;
                const float c1p = (-ab * as0p + aa * as1p) * inv_det;
                const float c0n = ( dd * as0n - ab * as1n) * inv_det;
                const float c1n = (-ab * as0n + aa * as1n) * inv_det;
                scp = ssp - c0p * as0p - c1p * as1p;
                scn = ssn - c0n * as0n - c1n * as1n;
            } else {
                // fallback c = As / aa is NOT the exact solution -> full quadratic
                const float inv_a = 1.0f / aa;
                const float c0p = as0p * inv_a, c1p = as1p * inv_a;
                const float c0n = as0n * inv_a, c1n = as1n * inv_a;
                scp = ssp - 2.0f * (c0p * as0p + c1p * as1p)
                    + c0p * c0p * aa + 2.0f * c0p * c1p * ab + c1p * c1p * dd;
                scn = ssn - 2.0f * (c0n * as0n + c1n * as1n)
                    + c0n * c0n * aa + 2.0f * c0n * c1n * ab + c1n * c1n * dd;
            }
            out[s]     = scp;
            out[B + s] = scn;
        }

        s = snext;
    }
}

extern "C" void kernel_launch(void* const* d_in, const int* in_sizes, int n_in,
                              void* d_out, int out_size) {
    const int*   pos_h    = (const int*)  d_in[0];
    const int*   pos_t    = (const int*)  d_in[1];
    const int*   pos_r    = (const int*)  d_in[2];
    const int*   neg_h    = (const int*)  d_in[3];
    const int*   neg_t    = (const int*)  d_in[4];
    // d_in[5] = neg_r (unused by the reference)
    const float* ent_emb  = (const float*)d_in[6];
    const float* heads    = (const float*)d_in[7];
    const float* bases    = (const float*)d_in[8];
    const int*   rel2head = (const int*)  d_in[9];
    const float* rel2mult = (const float*)d_in[10];
    float* out = (float*)d_out;

    const int B = in_sizes[0];
    const int total_warps = (B + SPW - 1) / SPW;
    const int blocks = (total_warps + WARPS_PER_BLOCK - 1) / WARPS_PER_BLOCK;
    transint_kernel<<<blocks, WARPS_PER_BLOCK * 32>>>(
        pos_h, pos_t, pos_r, neg_h, neg_t,
        ent_emb, heads, bases, rel2head, rel2mult, out, B);
}

// round 12
// speedup vs baseline: 1.4232x; 1.4232x over previous
#include <cuda_runtime.h>
#include <cuda_bf16.h>
#include <cstdint>

// TransINT scoring, single-pass quadratic form (R3 body), occupancy hint 4:
// the 64-register budget lets ptxas keep all 14 LDG.128s in flight in ONE
// batch (MLP~14) instead of two dependent waves of ~7 under the 48-reg/occ-5
// schedule. 32 warps x 14 in-flight > 40 warps x 7.
//   re = heads[rel2head[r]] * rel2mult[r]        (r = pos_r; neg_r unused)
//   s_pos = ent[ph] + re - ent[pt];  s_neg = ent[nh] + re - ent[nt]
//   A = bases[r] (2 x 256); c = ATA^{-1} (A.s)
//   exact-solution identity: ||s - A^T c||^2 = s.s - c.(A.s)
// out[0:B) = pos, out[B:2B) = neg (float32)

#define D 256
#define WARPS_PER_BLOCK 8

__global__ __launch_bounds__(WARPS_PER_BLOCK * 32, 4)
void transint_kernel(const int* __restrict__ pos_h,
                     const int* __restrict__ pos_t,
                     const int* __restrict__ pos_r,
                     const int* __restrict__ neg_h,
                     const int* __restrict__ neg_t,
                     const float* __restrict__ ent_emb,   // E x D
                     const float* __restrict__ heads,     // K x D
                     const float* __restrict__ bases,     // R x 2 x D
                     const int* __restrict__ rel2head,
                     const float* __restrict__ rel2mult,
                     float* __restrict__ out,
                     int B)
{
    const int warp = blockIdx.x * WARPS_PER_BLOCK + (threadIdx.x >> 5);
    if (warp >= B) return;
    const int lane = threadIdx.x & 31;

    // Per-sample indices (uniform across warp; broadcast loads)
    const int ph = pos_h[warp];
    const int pt = pos_t[warp];
    const int r  = pos_r[warp];
    const int nh = neg_h[warp];
    const int nt = neg_t[warp];
    const int hd = rel2head[r];
    const float mult = rel2mult[r];

    // Contiguous split: float4 index = lane and lane+32.
    // Each LDG.128 covers a 512B contiguous warp access (4 L1tex wavefronts).
    const int v0 = lane;
    const int v1 = lane + 32;

    const float4* __restrict__ Eph = (const float4*)(ent_emb + (size_t)ph * D);
    const float4* __restrict__ Ept = (const float4*)(ent_emb + (size_t)pt * D);
    const float4* __restrict__ Enh = (const float4*)(ent_emb + (size_t)nh * D);
    const float4* __restrict__ Ent = (const float4*)(ent_emb + (size_t)nt * D);
    const float4* __restrict__ Hd  = (const float4*)(heads   + (size_t)hd * D);
    const float4* __restrict__ A0p = (const float4*)(bases   + (size_t)r * 2 * D);
    const float4* __restrict__ A1p = (const float4*)(bases   + (size_t)r * 2 * D + D);

    // All 14 loads issued up-front; with a 64-reg budget they stay in ONE
    // in-flight batch (MLP ~14) covering DRAM latency once, not twice.
    float4 hp0 = Eph[v0], hp1 = Eph[v1];
    float4 tp0 = Ept[v0], tp1 = Ept[v1];
    float4 hn0 = Enh[v0], hn1 = Enh[v1];
    float4 tn0 = Ent[v0], tn1 = Ent[v1];
    float4 re0 = Hd[v0],  re1 = Hd[v1];
    float4 a00 = A0p[v0], a01 = A0p[v1];
    float4 a10 = A1p[v0], a11 = A1p[v1];

    // 9 streamed accumulators; no second pass over the data
    float aa = 0.f, ab = 0.f, dd = 0.f;
    float as0p = 0.f, as1p = 0.f, ssp = 0.f;
    float as0n = 0.f, as1n = 0.f, ssn = 0.f;

    {
        const float* hpp = (const float*)&hp0; const float* hpq = (const float*)&hp1;
        const float* tpp = (const float*)&tp0; const float* tpq = (const float*)&tp1;
        const float* hnp = (const float*)&hn0; const float* hnq = (const float*)&hn1;
        const float* tnp = (const float*)&tn0; const float* tnq = (const float*)&tn1;
        const float* rep = (const float*)&re0; const float* req = (const float*)&re1;
        const float* a0p = (const float*)&a00; const float* a0q = (const float*)&a01;
        const float* a1p = (const float*)&a10; const float* a1q = (const float*)&a11;
        #pragma unroll
        for (int i = 0; i < 4; i++) {
            {
                const float re = rep[i] * mult;
                const float sv = hpp[i] + re - tpp[i];
                const float nv = hnp[i] + re - tnp[i];
                const float A0 = a0p[i], A1 = a1p[i];
                aa   = fmaf(A0, A0, aa);
                ab   = fmaf(A0, A1, ab);
                dd   = fmaf(A1, A1, dd);
                as0p = fmaf(A0, sv, as0p);
                as1p = fmaf(A1, sv, as1p);
                ssp  = fmaf(sv, sv, ssp);
                as0n = fmaf(A0, nv, as0n);
                as1n = fmaf(A1, nv, as1n);
                ssn  = fmaf(nv, nv, ssn);
            }
            {
                const float re = req[i] * mult;
                const float sv = hpq[i] + re - tpq[i];
                const float nv = hnq[i] + re - tnq[i];
                const float A0 = a0q[i], A1 = a1q[i];
                aa   = fmaf(A0, A0, aa);
                ab   = fmaf(A0, A1, ab);
                dd   = fmaf(A1, A1, dd);
                as0p = fmaf(A0, sv, as0p);
                as1p = fmaf(A1, sv, as1p);
                ssp  = fmaf(sv, sv, ssp);
                as0n = fmaf(A0, nv, as0n);
                as1n = fmaf(A1, nv, as1n);
                ssn  = fmaf(nv, nv, ssn);
            }
        }
    }

    // Fused butterfly allreduce of 9 scalars
    #pragma unroll
    for (int m = 16; m > 0; m >>= 1) {
        aa   += __shfl_xor_sync(0xffffffffu, aa,   m);
        ab   += __shfl_xor_sync(0xffffffffu, ab,   m);
        dd   += __shfl_xor_sync(0xffffffffu, dd,   m);
        as0p += __shfl_xor_sync(0xffffffffu, as0p, m);
        as1p += __shfl_xor_sync(0xffffffffu, as1p, m);
        ssp  += __shfl_xor_sync(0xffffffffu, ssp,  m);
        as0n += __shfl_xor_sync(0xffffffffu, as0n, m);
        as1n += __shfl_xor_sync(0xffffffffu, as1n, m);
        ssn  += __shfl_xor_sync(0xffffffffu, ssn,  m);
    }

    if (lane == 0) {
        const float det = aa * dd - ab * ab;
        float scp, scn;
        if (det != 0.0f) {
            // exact normal-equation solve -> ||proj||^2 = ss - c . As
            const float inv_det = 1.0f / det;
            const float c0p = ( dd * as0p - ab * as1p) * inv_det;
            const float c1p = (-ab * as0p + aa * as1p) * inv_det;
            const float c0n = ( dd * as0n - ab * as1n) * inv_det;
            const float c1n = (-ab * as0n + aa * as1n) * inv_det;
            scp = ssp - c0p * as0p - c1p * as1p;
            scn = ssn - c0n * as0n - c1n * as1n;
        } else {
            // fallback c = As / aa is NOT the exact solution -> full quadratic
            const float inv_a = 1.0f / aa;
            const float c0p = as0p * inv_a, c1p = as1p * inv_a;
            const float c0n = as0n * inv_a, c1n = as1n * inv_a;
            scp = ssp - 2.0f * (c0p * as0p + c1p * as1p)
                + c0p * c0p * aa + 2.0f * c0p * c1p * ab + c1p * c1p * dd;
            scn = ssn - 2.0f * (c0n * as0n + c1n * as1n)
                + c0n * c0n * aa + 2.0f * c0n * c1n * ab + c1n * c1n * dd;
        }
        out[warp]     = scp;
        out[B + warp] = scn;
    }
}

extern "C" void kernel_launch(void* const* d_in, const int* in_sizes, int n_in,
                              void* d_out, int out_size) {
    const int*   pos_h    = (const int*)  d_in[0];
    const int*   pos_t    = (const int*)  d_in[1];
    const int*   pos_r    = (const int*)  d_in[2];
    const int*   neg_h    = (const int*)  d_in[3];
    const int*   neg_t    = (const int*)  d_in[4];
    // d_in[5] = neg_r (unused by the reference)
    const float* ent_emb  = (const float*)d_in[6];
    const float* heads    = (const float*)d_in[7];
    const float* bases    = (const float*)d_in[8];
    const int*   rel2head = (const int*)  d_in[9];
    const float* rel2mult = (const float*)d_in[10];
    float* out = (float*)d_out;

    const int B = in_sizes[0];
    const int blocks = (B + WARPS_PER_BLOCK - 1) / WARPS_PER_BLOCK;
    transint_kernel<<<blocks, WARPS_PER_BLOCK * 32>>>(
        pos_h, pos_t, pos_r, neg_h, neg_t,
        ent_emb, heads, bases, rel2head, rel2mult, out, B);
}